// round 1
// baseline (speedup 1.0000x reference)
#include <cuda_runtime.h>

#define BPTS   16384
#define ENC    63
#define LATD   256
#define NE     8
#define HIDD   256
#define OUTD   4
#define CHUNKD 32
#define EIND   95      // ENC + CHUNK
#define GIND   319     // ENC + LAT
#define EPSF   2.220446049250313e-16f

// ---------------- scratch (static device globals; no runtime alloc) ----------
__device__ int   g_count[NE];
__device__ int   g_list[NE][BPTS];
__device__ float g_gv[BPTS];

// ---------------- GEMM micro-kernel helpers ---------------------------------
// 64x256 output tile per CTA, 256 threads, 8x8 microtile per thread.
// Weight tiles (16 x 256 fp32) double-buffered in smem.

__device__ __forceinline__ void load_wtile(const float* __restrict__ W, int t,
                                           int k_real, float* dst, int tid) {
#pragma unroll
    for (int p = 0; p < 4; p++) {
        int f4  = tid + p * 256;      // float4 index within 16x256 tile (1024 total)
        int row = f4 >> 6;            // /64 float4 per row
        int k   = t * 16 + row;
        float4 v = make_float4(0.f, 0.f, 0.f, 0.f);
        if (k < k_real) v = *(const float4*)(W + (size_t)k * 256 + (f4 & 63) * 4);
        *(float4*)(dst + f4 * 4) = v;
    }
}

// Accumulate S[64 x k_real] @ W[k_real x 256] into acc (k_pad multiple of 16).
__device__ __forceinline__ void gemm_acc(const float* __restrict__ S, int ldS,
                                         const float* __restrict__ W,
                                         int k_pad, int k_real,
                                         float* w_s, float acc[8][8], int tid) {
    const int tcol = tid & 31, trow = tid >> 5;
    const int ntiles = k_pad >> 4;
    load_wtile(W, 0, k_real, w_s, tid);
    __syncthreads();
    for (int t = 0; t < ntiles; t++) {
        const float* cur = w_s + (t & 1) * 4096;
        if (t + 1 < ntiles)
            load_wtile(W, t + 1, k_real, w_s + ((t + 1) & 1) * 4096, tid);
        const float* Sb = S + t * 16;
#pragma unroll
        for (int kk = 0; kk < 16; kk += 4) {
            float4 a4[8];
#pragma unroll
            for (int i = 0; i < 8; i++)
                a4[i] = *(const float4*)(Sb + (trow * 8 + i) * ldS + kk);
#pragma unroll
            for (int u = 0; u < 4; u++) {
                float4 b0 = *(const float4*)(cur + (kk + u) * 256 + tcol * 8);
                float4 b1 = *(const float4*)(cur + (kk + u) * 256 + tcol * 8 + 4);
#pragma unroll
                for (int i = 0; i < 8; i++) {
                    float av = (u == 0) ? a4[i].x : (u == 1) ? a4[i].y
                             : (u == 2) ? a4[i].z : a4[i].w;
                    acc[i][0] += av * b0.x;
                    acc[i][1] += av * b0.y;
                    acc[i][2] += av * b0.z;
                    acc[i][3] += av * b0.w;
                    acc[i][4] += av * b1.x;
                    acc[i][5] += av * b1.y;
                    acc[i][6] += av * b1.z;
                    acc[i][7] += av * b1.w;
                }
            }
        }
        __syncthreads();
    }
}

__device__ __forceinline__ void zero_acc(float acc[8][8]) {
#pragma unroll
    for (int i = 0; i < 8; i++)
#pragma unroll
        for (int j = 0; j < 8; j++) acc[i][j] = 0.f;
}

// relu(acc + bias) -> dst (ld 256), vectorized conflict-free stores
__device__ __forceinline__ void store_relu(const float acc[8][8],
                                           const float* __restrict__ bias,
                                           float* dst, int tid) {
    const int tcol = tid & 31, trow = tid >> 5;
    float4 bb0 = *(const float4*)(bias + tcol * 8);
    float4 bb1 = *(const float4*)(bias + tcol * 8 + 4);
#pragma unroll
    for (int i = 0; i < 8; i++) {
        float4 v0, v1;
        v0.x = fmaxf(acc[i][0] + bb0.x, 0.f);
        v0.y = fmaxf(acc[i][1] + bb0.y, 0.f);
        v0.z = fmaxf(acc[i][2] + bb0.z, 0.f);
        v0.w = fmaxf(acc[i][3] + bb0.w, 0.f);
        v1.x = fmaxf(acc[i][4] + bb1.x, 0.f);
        v1.y = fmaxf(acc[i][5] + bb1.y, 0.f);
        v1.z = fmaxf(acc[i][6] + bb1.z, 0.f);
        v1.w = fmaxf(acc[i][7] + bb1.w, 0.f);
        *(float4*)(dst + (trow * 8 + i) * 256 + tcol * 8)     = v0;
        *(float4*)(dst + (trow * 8 + i) * 256 + tcol * 8 + 4) = v1;
    }
}

// ---------------- kernel 0: reset routing counters ---------------------------
__global__ void reset_kernel() {
    if (threadIdx.x < NE) g_count[threadIdx.x] = 0;
}

// ---------------- kernel 1: gate network + routing ---------------------------
// smem: gin[64*320] (reused as h2 with ld 257) | hbuf[64*256] | wtiles[2*16*256]
#define GATE_SMEM_F (20480 + 16384 + 8192)

__global__ __launch_bounds__(256, 1) void gate_kernel(
    const float* __restrict__ x,  const float* __restrict__ sl,
    const float* __restrict__ gw1, const float* __restrict__ gb1,
    const float* __restrict__ gw2, const float* __restrict__ gb2,
    const float* __restrict__ lng, const float* __restrict__ lnb,
    const float* __restrict__ gw3, const float* __restrict__ gb3) {
    extern __shared__ float sm[];
    float* gin  = sm;                  // 64*320 (GEMM1 src), later h2 (ld 257)
    float* hbuf = sm + 20480;          // 64*256 (h1), later logits
    float* wsm  = sm + 20480 + 16384;  // 2*16*256
    const int tid  = threadIdx.x;
    const int row0 = blockIdx.x * 64;
    const int tcol = tid & 31, trow = tid >> 5;

    // gather g_in = concat(x, shape_latent), pad col 319 with 0
    for (int idx = tid; idx < 64 * 320; idx += 256) {
        int r = idx / 320, c = idx - r * 320;
        int gi = row0 + r;
        float v = 0.f;
        if (c < 63)       v = x[gi * 63 + c];
        else if (c < 319) v = sl[gi * 256 + (c - 63)];
        gin[idx] = v;
    }
    __syncthreads();

    float acc[8][8];

    // h1 = relu(g_in @ gw1 + gb1)
    zero_acc(acc);
    gemm_acc(gin, 320, gw1, 320, 319, wsm, acc, tid);
    store_relu(acc, gb1, hbuf, tid);
    __syncthreads();

    // h2 = h1 @ gw2 + gb2  -> stored at ld 257 (bank-conflict-free row scans)
    zero_acc(acc);
    gemm_acc(hbuf, 256, gw2, 256, 256, wsm, acc, tid);
#pragma unroll
    for (int j = 0; j < 8; j++) {
        int c = tcol * 8 + j;
        float b = gb2[c];
#pragma unroll
        for (int i = 0; i < 8; i++)
            gin[(trow * 8 + i) * 257 + c] = acc[i][j] + b;
    }
    __syncthreads();

    // LayerNorm per row: 4 threads/row, two-pass (mean, then var)
    {
        int r = tid >> 2, sub = tid & 3;
        float* h2r = gin + r * 257;
        float s = 0.f;
#pragma unroll 8
        for (int k = 0; k < 64; k++) s += h2r[sub + 4 * k];
        s += __shfl_xor_sync(0xffffffffu, s, 1);
        s += __shfl_xor_sync(0xffffffffu, s, 2);
        float mu = s * (1.f / 256.f);
        float vv = 0.f;
#pragma unroll 8
        for (int k = 0; k < 64; k++) {
            float d = h2r[sub + 4 * k] - mu;
            vv += d * d;
        }
        vv += __shfl_xor_sync(0xffffffffu, vv, 1);
        vv += __shfl_xor_sync(0xffffffffu, vv, 2);
        float rstd = rsqrtf(vv * (1.f / 256.f) + 1e-5f);
#pragma unroll 8
        for (int k = 0; k < 64; k++) {
            int c = sub + 4 * k;
            float nv = (h2r[c] - mu) * rstd;
            h2r[c] = nv * lng[c] + lnb[c];
        }
    }
    __syncthreads();

    // logits = h2 @ gw3 + gb3  (64 rows x 8 experts) -> hbuf
    for (int task = tid; task < 512; task += 256) {
        int r = task >> 3, e = task & 7;
        float d = gb3[e];
        const float* h2r = gin + r * 257;
#pragma unroll 8
        for (int k = 0; k < 256; k++) d += h2r[k] * gw3[k * 8 + e];
        hbuf[r * 8 + e] = d;
    }
    __syncthreads();

    // softmax / argmax / append to expert list
    if (tid < 64) {
        int gi = row0 + tid;
        const float* lg = hbuf + tid * 8;
        float best = lg[0];
        int bi = 0;
#pragma unroll
        for (int e = 1; e < 8; e++) {
            float v = lg[e];
            if (v > best) { best = v; bi = e; }   // first-max like jnp.argmax
        }
        float ssum = 0.f;
#pragma unroll
        for (int e = 0; e < 8; e++) ssum += expf(lg[e] - best);
        g_gv[gi] = 1.f / ssum;                    // top gate value
        int pos = atomicAdd(&g_count[bi], 1);
        g_list[bi][pos] = gi;
    }
}

// ---------------- kernel 2: routed expert MLP --------------------------------
// smem: h0[64*96] | act[64*256] | wtiles[2*16*256]
#define EXP_SMEM_F (6144 + 16384 + 8192)

__global__ __launch_bounds__(256, 1) void expert_kernel(
    const float* __restrict__ x,  const float* __restrict__ sl,
    const float* __restrict__ ew0, const float* __restrict__ eb0,
    const float* __restrict__ ew1, const float* __restrict__ eb1,
    const float* __restrict__ ew2, const float* __restrict__ eb2,
    const float* __restrict__ ew3, const float* __restrict__ eb3,
    const float* __restrict__ ew4, const float* __restrict__ eb4,
    const float* __restrict__ ew5, const float* __restrict__ eb5,
    const float* __restrict__ ew6, const float* __restrict__ eb6,
    const float* __restrict__ ewo, const float* __restrict__ ebo,
    float* __restrict__ out) {
    const int e = blockIdx.y;
    const int n = g_count[e];
    const int start = blockIdx.x * 64;
    if (start >= n) return;
    const int nrows = min(64, n - start);

    extern __shared__ float sm[];
    float* h0s  = sm;                   // 64*96
    float* acts = sm + 6144;            // 64*256
    float* wsm  = sm + 6144 + 16384;    // 2*16*256
    __shared__ int ridx[64];
    const int tid = threadIdx.x;

    if (tid < 64) ridx[tid] = (tid < nrows) ? g_list[e][start + tid] : -1;
    __syncthreads();

    // gather h0 = concat(x, latent chunk e), pad col 95 with 0
    for (int idx = tid; idx < 64 * 96; idx += 256) {
        int r = idx / 96, c = idx - r * 96;
        int gi = ridx[r];
        float v = 0.f;
        if (gi >= 0) {
            if (c < 63)      v = x[gi * 63 + c];
            else if (c < 95) v = sl[gi * 256 + e * CHUNKD + (c - 63)];
        }
        h0s[idx] = v;
    }
    __syncthreads();

    float acc[8][8];

    // layer 0: h0 (K=95) -> 256
    zero_acc(acc);
    gemm_acc(h0s, 96, ew0 + (size_t)e * 95 * 256, 96, 95, wsm, acc, tid);
    store_relu(acc, eb0 + e * 256, acts, tid);

    // layers 1..4: 256 -> 256
    const float* wl[4] = { ew1, ew2, ew3, ew4 };
    const float* bl[4] = { eb1, eb2, eb3, eb4 };
    for (int l = 0; l < 4; l++) {
        zero_acc(acc);
        gemm_acc(acts, 256, wl[l] + (size_t)e * 65536, 256, 256, wsm, acc, tid);
        store_relu(acc, bl[l] + e * 256, acts, tid);
    }

    // layer 5 (skip): concat(act, h0) @ ew5[351,256], done as two passes
    zero_acc(acc);
    gemm_acc(acts, 256, ew5 + (size_t)e * 351 * 256, 256, 256, wsm, acc, tid);
    gemm_acc(h0s, 96, ew5 + (size_t)e * 351 * 256 + 256 * 256, 96, 95, wsm, acc, tid);
    store_relu(acc, eb5 + e * 256, acts, tid);

    // layer 6
    zero_acc(acc);
    gemm_acc(acts, 256, ew6 + (size_t)e * 65536, 256, 256, wsm, acc, tid);
    store_relu(acc, eb6 + e * 256, acts, tid);
    __syncthreads();

    // output head: y = act @ ewo[e] + ebo[e]; combine with gate
    {
        int r = tid >> 2, o = tid & 3;
        if (r < nrows) {
            float d = ebo[e * 4 + o];
            const float* ar = acts + r * 256;
            const float* wo = ewo + (size_t)e * 1024 + o;
#pragma unroll 8
            for (int k = 0; k < 256; k++) d += ar[k] * wo[k * 4];
            int gi = ridx[r];
            float comb = g_gv[gi] * expf(d);
            if (comb == 0.f) comb = EPSF;
            out[gi * 4 + o] = logf(comb);
        }
    }
}

// ---------------- launch -----------------------------------------------------
extern "C" void kernel_launch(void* const* d_in, const int* in_sizes, int n_in,
                              void* d_out, int out_size) {
    const float* x   = (const float*)d_in[0];
    const float* sl  = (const float*)d_in[1];
    const float* gw1 = (const float*)d_in[2];
    const float* gb1 = (const float*)d_in[3];
    const float* gw2 = (const float*)d_in[4];
    const float* gb2 = (const float*)d_in[5];
    const float* lng = (const float*)d_in[6];
    const float* lnb = (const float*)d_in[7];
    const float* gw3 = (const float*)d_in[8];
    const float* gb3 = (const float*)d_in[9];
    const float* ew0 = (const float*)d_in[10];
    const float* eb0 = (const float*)d_in[11];
    const float* ew1 = (const float*)d_in[12];
    const float* eb1 = (const float*)d_in[13];
    const float* ew2 = (const float*)d_in[14];
    const float* eb2 = (const float*)d_in[15];
    const float* ew3 = (const float*)d_in[16];
    const float* eb3 = (const float*)d_in[17];
    const float* ew4 = (const float*)d_in[18];
    const float* eb4 = (const float*)d_in[19];
    const float* ew5 = (const float*)d_in[20];
    const float* eb5 = (const float*)d_in[21];
    const float* ew6 = (const float*)d_in[22];
    const float* eb6 = (const float*)d_in[23];
    const float* ewo = (const float*)d_in[24];
    const float* ebo = (const float*)d_in[25];
    float* out = (float*)d_out;

    cudaFuncSetAttribute(gate_kernel, cudaFuncAttributeMaxDynamicSharedMemorySize,
                         GATE_SMEM_F * 4);
    cudaFuncSetAttribute(expert_kernel, cudaFuncAttributeMaxDynamicSharedMemorySize,
                         EXP_SMEM_F * 4);

    reset_kernel<<<1, 32>>>();
    gate_kernel<<<BPTS / 64, 256, GATE_SMEM_F * 4>>>(x, sl, gw1, gb1, gw2, gb2,
                                                     lng, lnb, gw3, gb3);
    expert_kernel<<<dim3(BPTS / 64, NE), 256, EXP_SMEM_F * 4>>>(
        x, sl, ew0, eb0, ew1, eb1, ew2, eb2, ew3, eb3, ew4, eb4,
        ew5, eb5, ew6, eb6, ewo, ebo, out);
}

// round 2
// speedup vs baseline: 1.0081x; 1.0081x over previous
#include <cuda_runtime.h>

#define BPTS   16384
#define ENC    63
#define LATD   256
#define NE     8
#define HIDD   256
#define OUTD   4
#define CHUNKD 32
#define EIND   95      // ENC + CHUNK
#define GIND   319     // ENC + LAT
#define EPSF   2.220446049250313e-16f

// ---------------- scratch (static device globals; no runtime alloc) ----------
__device__ int   g_count[NE];
__device__ int   g_list[NE][BPTS];
__device__ float g_gv[BPTS];

// ---------------- packed f32x2 helpers ---------------------------------------
typedef unsigned long long u64;

__device__ __forceinline__ void ffma2(u64& d, u64 a, u64 b) {
    asm("fma.rn.f32x2 %0, %1, %2, %0;" : "+l"(d) : "l"(a), "l"(b));
}
__device__ __forceinline__ u64 dup2(float v) {
    u64 r;
    asm("mov.b64 %0, {%1, %1};" : "=l"(r) : "r"(__float_as_uint(v)));
    return r;
}
__device__ __forceinline__ float2 unpk(u64 v) {
    float2 f;
    asm("mov.b64 {%0, %1}, %2;" : "=f"(f.x), "=f"(f.y) : "l"(v));
    return f;
}

// ---------------- GEMM micro-kernel helpers ---------------------------------
// 64x256 output tile per CTA, 256 threads, 8x8 microtile per thread.
// Accumulators held as 8x4 packed f32x2 pairs. Weight tiles (16x256 fp32)
// double-buffered in smem; B operands read as pre-paired u64 from smem.

__device__ __forceinline__ void load_wtile(const float* __restrict__ W, int t,
                                           int k_real, float* dst, int tid) {
#pragma unroll
    for (int p = 0; p < 4; p++) {
        int f4  = tid + p * 256;      // float4 index within 16x256 tile (1024 total)
        int row = f4 >> 6;            // /64 float4 per row
        int k   = t * 16 + row;
        float4 v = make_float4(0.f, 0.f, 0.f, 0.f);
        if (k < k_real) v = *(const float4*)(W + (size_t)k * 256 + (f4 & 63) * 4);
        *(float4*)(dst + f4 * 4) = v;
    }
}

// Accumulate S[64 x k_real] @ W[k_real x 256] into packed acc.
__device__ __forceinline__ void gemm_acc(const float* __restrict__ S, int ldS,
                                         const float* __restrict__ W,
                                         int k_pad, int k_real,
                                         float* w_s, u64 acc[8][4], int tid) {
    const int tcol = tid & 31, trow = tid >> 5;
    const int ntiles = k_pad >> 4;
    load_wtile(W, 0, k_real, w_s, tid);
    __syncthreads();
    for (int t = 0; t < ntiles; t++) {
        const float* cur = w_s + (t & 1) * 4096;
        if (t + 1 < ntiles)
            load_wtile(W, t + 1, k_real, w_s + ((t + 1) & 1) * 4096, tid);
        const float* Sb = S + t * 16;
#pragma unroll
        for (int kk = 0; kk < 16; kk += 4) {
            float4 a4[8];
#pragma unroll
            for (int i = 0; i < 8; i++)
                a4[i] = *(const float4*)(Sb + (trow * 8 + i) * ldS + kk);
#pragma unroll
            for (int u = 0; u < 4; u++) {
                const u64* bp = (const u64*)(cur + (kk + u) * 256 + tcol * 8);
                u64 b0 = bp[0], b1 = bp[1], b2 = bp[2], b3 = bp[3];
#pragma unroll
                for (int i = 0; i < 8; i++) {
                    float av = (u == 0) ? a4[i].x : (u == 1) ? a4[i].y
                             : (u == 2) ? a4[i].z : a4[i].w;
                    u64 avv = dup2(av);
                    ffma2(acc[i][0], avv, b0);
                    ffma2(acc[i][1], avv, b1);
                    ffma2(acc[i][2], avv, b2);
                    ffma2(acc[i][3], avv, b3);
                }
            }
        }
        __syncthreads();
    }
}

__device__ __forceinline__ void zero_acc(u64 acc[8][4]) {
#pragma unroll
    for (int i = 0; i < 8; i++)
#pragma unroll
        for (int j = 0; j < 4; j++) acc[i][j] = 0ull;
}

// relu(acc + bias) -> dst (ld 256), vectorized conflict-free stores
__device__ __forceinline__ void store_relu(const u64 acc[8][4],
                                           const float* __restrict__ bias,
                                           float* dst, int tid) {
    const int tcol = tid & 31, trow = tid >> 5;
    float4 bb0 = *(const float4*)(bias + tcol * 8);
    float4 bb1 = *(const float4*)(bias + tcol * 8 + 4);
#pragma unroll
    for (int i = 0; i < 8; i++) {
        float2 p0 = unpk(acc[i][0]), p1 = unpk(acc[i][1]);
        float2 p2 = unpk(acc[i][2]), p3 = unpk(acc[i][3]);
        float4 v0, v1;
        v0.x = fmaxf(p0.x + bb0.x, 0.f);
        v0.y = fmaxf(p0.y + bb0.y, 0.f);
        v0.z = fmaxf(p1.x + bb0.z, 0.f);
        v0.w = fmaxf(p1.y + bb0.w, 0.f);
        v1.x = fmaxf(p2.x + bb1.x, 0.f);
        v1.y = fmaxf(p2.y + bb1.y, 0.f);
        v1.z = fmaxf(p3.x + bb1.z, 0.f);
        v1.w = fmaxf(p3.y + bb1.w, 0.f);
        *(float4*)(dst + (trow * 8 + i) * 256 + tcol * 8)     = v0;
        *(float4*)(dst + (trow * 8 + i) * 256 + tcol * 8 + 4) = v1;
    }
}

// ---------------- kernel 0: reset routing counters ---------------------------
__global__ void reset_kernel() {
    if (threadIdx.x < NE) g_count[threadIdx.x] = 0;
}

// ---------------- kernel 1: gate network + routing ---------------------------
// smem: gin[64*320] (reused as h2 with ld 257) | hbuf[64*256] | wtiles[2*16*256]
#define GATE_SMEM_F (20480 + 16384 + 8192)

__global__ __launch_bounds__(256, 1) void gate_kernel(
    const float* __restrict__ x,  const float* __restrict__ sl,
    const float* __restrict__ gw1, const float* __restrict__ gb1,
    const float* __restrict__ gw2, const float* __restrict__ gb2,
    const float* __restrict__ lng, const float* __restrict__ lnb,
    const float* __restrict__ gw3, const float* __restrict__ gb3) {
    extern __shared__ float sm[];
    float* gin  = sm;                  // 64*320 (GEMM1 src), later h2 (ld 257)
    float* hbuf = sm + 20480;          // 64*256 (h1), later logits
    float* wsm  = sm + 20480 + 16384;  // 2*16*256
    const int tid  = threadIdx.x;
    const int row0 = blockIdx.x * 64;
    const int tcol = tid & 31, trow = tid >> 5;

    // gather g_in = concat(x, shape_latent), pad col 319 with 0
    for (int idx = tid; idx < 64 * 320; idx += 256) {
        int r = idx / 320, c = idx - r * 320;
        int gi = row0 + r;
        float v = 0.f;
        if (c < 63)       v = x[gi * 63 + c];
        else if (c < 319) v = sl[gi * 256 + (c - 63)];
        gin[idx] = v;
    }
    __syncthreads();

    u64 acc[8][4];

    // h1 = relu(g_in @ gw1 + gb1)
    zero_acc(acc);
    gemm_acc(gin, 320, gw1, 320, 319, wsm, acc, tid);
    store_relu(acc, gb1, hbuf, tid);
    __syncthreads();

    // h2 = h1 @ gw2 + gb2  -> stored at ld 257 (bank-conflict-free row scans)
    zero_acc(acc);
    gemm_acc(hbuf, 256, gw2, 256, 256, wsm, acc, tid);
#pragma unroll
    for (int p = 0; p < 4; p++) {
#pragma unroll
        for (int i = 0; i < 8; i++) {
            float2 f = unpk(acc[i][p]);
            int c0 = tcol * 8 + p * 2;
            gin[(trow * 8 + i) * 257 + c0]     = f.x + gb2[c0];
            gin[(trow * 8 + i) * 257 + c0 + 1] = f.y + gb2[c0 + 1];
        }
    }
    __syncthreads();

    // LayerNorm per row: 4 threads/row, two-pass (mean, then var)
    {
        int r = tid >> 2, sub = tid & 3;
        float* h2r = gin + r * 257;
        float s = 0.f;
#pragma unroll 8
        for (int k = 0; k < 64; k++) s += h2r[sub + 4 * k];
        s += __shfl_xor_sync(0xffffffffu, s, 1);
        s += __shfl_xor_sync(0xffffffffu, s, 2);
        float mu = s * (1.f / 256.f);
        float vv = 0.f;
#pragma unroll 8
        for (int k = 0; k < 64; k++) {
            float d = h2r[sub + 4 * k] - mu;
            vv += d * d;
        }
        vv += __shfl_xor_sync(0xffffffffu, vv, 1);
        vv += __shfl_xor_sync(0xffffffffu, vv, 2);
        float rstd = rsqrtf(vv * (1.f / 256.f) + 1e-5f);
#pragma unroll 8
        for (int k = 0; k < 64; k++) {
            int c = sub + 4 * k;
            float nv = (h2r[c] - mu) * rstd;
            h2r[c] = nv * lng[c] + lnb[c];
        }
    }
    __syncthreads();

    // logits = h2 @ gw3 + gb3  (64 rows x 8 experts) -> hbuf
    for (int task = tid; task < 512; task += 256) {
        int r = task >> 3, e = task & 7;
        float d = gb3[e];
        const float* h2r = gin + r * 257;
#pragma unroll 8
        for (int k = 0; k < 256; k++) d += h2r[k] * gw3[k * 8 + e];
        hbuf[r * 8 + e] = d;
    }
    __syncthreads();

    // softmax / argmax / append to expert list
    if (tid < 64) {
        int gi = row0 + tid;
        const float* lg = hbuf + tid * 8;
        float best = lg[0];
        int bi = 0;
#pragma unroll
        for (int e = 1; e < 8; e++) {
            float v = lg[e];
            if (v > best) { best = v; bi = e; }   // first-max like jnp.argmax
        }
        float ssum = 0.f;
#pragma unroll
        for (int e = 0; e < 8; e++) ssum += expf(lg[e] - best);
        g_gv[gi] = 1.f / ssum;                    // top gate value
        int pos = atomicAdd(&g_count[bi], 1);
        g_list[bi][pos] = gi;
    }
}

// ---------------- kernel 2: routed expert MLP --------------------------------
// Compact grid: sum_e ceil(n_e/64) <= 256+8 = 264 tiles. Each CTA maps its
// linear tile id to (expert, tile) by prefix-scanning g_count.
// smem: h0[64*96] | act[64*256] | wtiles[2*16*256]
#define EXP_SMEM_F (6144 + 16384 + 8192)
#define EXP_TILES  (BPTS / 64 + NE)

__global__ __launch_bounds__(256, 1) void expert_kernel(
    const float* __restrict__ x,  const float* __restrict__ sl,
    const float* __restrict__ ew0, const float* __restrict__ eb0,
    const float* __restrict__ ew1, const float* __restrict__ eb1,
    const float* __restrict__ ew2, const float* __restrict__ eb2,
    const float* __restrict__ ew3, const float* __restrict__ eb3,
    const float* __restrict__ ew4, const float* __restrict__ eb4,
    const float* __restrict__ ew5, const float* __restrict__ eb5,
    const float* __restrict__ ew6, const float* __restrict__ eb6,
    const float* __restrict__ ewo, const float* __restrict__ ebo,
    float* __restrict__ out) {
    // map linear tile id -> (expert, row range)
    int t = blockIdx.x;
    int e = 0, base = 0, n = 0;
#pragma unroll
    for (int q = 0; q < NE; q++) {
        int cnt = g_count[q];
        int T   = (cnt + 63) >> 6;
        if (e == 0 && t < base + T) { /* found below via flags */ }
        base += T;
    }
    // redo scan sequentially (cheap, 8 iterations)
    base = 0;
    for (e = 0; e < NE; e++) {
        n = g_count[e];
        int T = (n + 63) >> 6;
        if (t < base + T) break;
        base += T;
    }
    if (e == NE) return;
    const int start = (t - base) * 64;
    const int nrows = min(64, n - start);

    extern __shared__ float sm[];
    float* h0s  = sm;                   // 64*96
    float* acts = sm + 6144;            // 64*256
    float* wsm  = sm + 6144 + 16384;    // 2*16*256
    __shared__ int ridx[64];
    const int tid = threadIdx.x;

    if (tid < 64) ridx[tid] = (tid < nrows) ? g_list[e][start + tid] : -1;
    __syncthreads();

    // gather h0 = concat(x, latent chunk e), pad col 95 with 0
    for (int idx = tid; idx < 64 * 96; idx += 256) {
        int r = idx / 96, c = idx - r * 96;
        int gi = ridx[r];
        float v = 0.f;
        if (gi >= 0) {
            if (c < 63)      v = x[gi * 63 + c];
            else if (c < 95) v = sl[gi * 256 + e * CHUNKD + (c - 63)];
        }
        h0s[idx] = v;
    }
    __syncthreads();

    u64 acc[8][4];

    // layer 0: h0 (K=95) -> 256
    zero_acc(acc);
    gemm_acc(h0s, 96, ew0 + (size_t)e * 95 * 256, 96, 95, wsm, acc, tid);
    store_relu(acc, eb0 + e * 256, acts, tid);

    // layers 1..4: 256 -> 256
    const float* wl[4] = { ew1, ew2, ew3, ew4 };
    const float* bl[4] = { eb1, eb2, eb3, eb4 };
    for (int l = 0; l < 4; l++) {
        zero_acc(acc);
        gemm_acc(acts, 256, wl[l] + (size_t)e * 65536, 256, 256, wsm, acc, tid);
        store_relu(acc, bl[l] + e * 256, acts, tid);
    }

    // layer 5 (skip): concat(act, h0) @ ew5[351,256], done as two passes
    zero_acc(acc);
    gemm_acc(acts, 256, ew5 + (size_t)e * 351 * 256, 256, 256, wsm, acc, tid);
    gemm_acc(h0s, 96, ew5 + (size_t)e * 351 * 256 + 256 * 256, 96, 95, wsm, acc, tid);
    store_relu(acc, eb5 + e * 256, acts, tid);

    // layer 6
    zero_acc(acc);
    gemm_acc(acts, 256, ew6 + (size_t)e * 65536, 256, 256, wsm, acc, tid);
    store_relu(acc, eb6 + e * 256, acts, tid);
    __syncthreads();

    // output head: y = act @ ewo[e] + ebo[e]; combine with gate
    {
        int r = tid >> 2, o = tid & 3;
        if (r < nrows) {
            float d = ebo[e * 4 + o];
            const float* ar = acts + r * 256;
            const float* wo = ewo + (size_t)e * 1024 + o;
#pragma unroll 8
            for (int k = 0; k < 256; k++) d += ar[k] * wo[k * 4];
            int gi = ridx[r];
            float comb = g_gv[gi] * expf(d);
            if (comb == 0.f) comb = EPSF;
            out[gi * 4 + o] = logf(comb);
        }
    }
}

// ---------------- launch -----------------------------------------------------
extern "C" void kernel_launch(void* const* d_in, const int* in_sizes, int n_in,
                              void* d_out, int out_size) {
    const float* x   = (const float*)d_in[0];
    const float* sl  = (const float*)d_in[1];
    const float* gw1 = (const float*)d_in[2];
    const float* gb1 = (const float*)d_in[3];
    const float* gw2 = (const float*)d_in[4];
    const float* gb2 = (const float*)d_in[5];
    const float* lng = (const float*)d_in[6];
    const float* lnb = (const float*)d_in[7];
    const float* gw3 = (const float*)d_in[8];
    const float* gb3 = (const float*)d_in[9];
    const float* ew0 = (const float*)d_in[10];
    const float* eb0 = (const float*)d_in[11];
    const float* ew1 = (const float*)d_in[12];
    const float* eb1 = (const float*)d_in[13];
    const float* ew2 = (const float*)d_in[14];
    const float* eb2 = (const float*)d_in[15];
    const float* ew3 = (const float*)d_in[16];
    const float* eb3 = (const float*)d_in[17];
    const float* ew4 = (const float*)d_in[18];
    const float* eb4 = (const float*)d_in[19];
    const float* ew5 = (const float*)d_in[20];
    const float* eb5 = (const float*)d_in[21];
    const float* ew6 = (const float*)d_in[22];
    const float* eb6 = (const float*)d_in[23];
    const float* ewo = (const float*)d_in[24];
    const float* ebo = (const float*)d_in[25];
    float* out = (float*)d_out;

    cudaFuncSetAttribute(gate_kernel, cudaFuncAttributeMaxDynamicSharedMemorySize,
                         GATE_SMEM_F * 4);
    cudaFuncSetAttribute(expert_kernel, cudaFuncAttributeMaxDynamicSharedMemorySize,
                         EXP_SMEM_F * 4);

    reset_kernel<<<1, 32>>>();
    gate_kernel<<<BPTS / 64, 256, GATE_SMEM_F * 4>>>(x, sl, gw1, gb1, gw2, gb2,
                                                     lng, lnb, gw3, gb3);
    expert_kernel<<<EXP_TILES, 256, EXP_SMEM_F * 4>>>(
        x, sl, ew0, eb0, ew1, eb1, ew2, eb2, ew3, eb3, ew4, eb4,
        ew5, eb5, ew6, eb6, ewo, ebo, out);
}

// round 3
// speedup vs baseline: 1.6662x; 1.6528x over previous
#include <cuda_runtime.h>
#include <cuda_bf16.h>

#define BPTS   16384
#define ENC    63
#define NE     8
#define CHUNKD 32
#define EPSF   2.220446049250313e-16f
#define WROWS  1728           // padded K rows per expert: 96+4*256+256+96+256
typedef unsigned int u32;
typedef unsigned long long u64;

// ---------------- scratch (static device globals) ----------------------------
__device__ int   g_count[NE];
__device__ int   g_list[NE][BPTS];
__device__ float g_gv[BPTS];
__device__ unsigned short g_wh[NE * WROWS * 256];   // bf16 hi weights
__device__ unsigned short g_wl[NE * WROWS * 256];   // bf16 lo weights

// ---------------- tensor-core helpers ----------------------------------------
__device__ __forceinline__ void mma_bf16(float d[4], u32 a0, u32 a1, u32 a2, u32 a3,
                                         u32 b0, u32 b1) {
    asm volatile(
        "mma.sync.aligned.m16n8k16.row.col.f32.bf16.bf16.f32 "
        "{%0,%1,%2,%3}, {%4,%5,%6,%7}, {%8,%9}, {%0,%1,%2,%3};"
        : "+f"(d[0]), "+f"(d[1]), "+f"(d[2]), "+f"(d[3])
        : "r"(a0), "r"(a1), "r"(a2), "r"(a3), "r"(b0), "r"(b1));
}
__device__ __forceinline__ void ldsm4t(u32 r[4], u32 addr) {
    asm volatile("ldmatrix.sync.aligned.m8n8.x4.trans.shared.b16 {%0,%1,%2,%3}, [%4];"
                 : "=r"(r[0]), "=r"(r[1]), "=r"(r[2]), "=r"(r[3]) : "r"(addr));
}
__device__ __forceinline__ void split2(float f0, float f1, u32& h, u32& l) {
    __nv_bfloat162 hh = __floats2bfloat162_rn(f0, f1);
    float2 hf = __bfloat1622float2(hh);
    __nv_bfloat162 ll = __floats2bfloat162_rn(f0 - hf.x, f1 - hf.y);
    h = *(u32*)&hh;  l = *(u32*)&ll;
}

// ---------------- split-bf16 GEMM: acc[64x256] += src[64xK] @ W[Kx256] --------
// 256 threads, warp grid 2(M)x4(N); warp tile m32 x n64.
// Weights: bf16 hi/lo, K padded to mult of 16, staged to smem double-buffered.
#define WBSTRIDE 264
#define WBPLANE  (16 * WBSTRIDE)     // elements per 16x256 staged plane

__device__ __forceinline__ void gemm_tc(
    float (&acc)[2][8][4],
    const float* __restrict__ src, int sst, int K,
    const unsigned short* __restrict__ Wh, const unsigned short* __restrict__ Wl,
    unsigned short* wb, u32 wb_u32, int tid)
{
    const int lane = tid & 31, wid = tid >> 5;
    const int m0 = (wid & 1) * 32, n_off = (wid >> 1) * 64;
    const int g = lane >> 2, tt = lane & 3;
    const int b_off = (lane & 15) * WBSTRIDE + n_off + (lane >> 4) * 8;
    const int nt = K >> 4;
    const int r0 = tid >> 5,        c0 = (tid & 31) * 8;
    const int r1 = (tid + 256) >> 5, c1 = ((tid + 256) & 31) * 8;

    // stage chunk 0 into buf 0
    *(uint4*)(wb + 0 * WBPLANE + r0 * WBSTRIDE + c0) = *(const uint4*)(Wh + r0 * 256 + c0);
    *(uint4*)(wb + 0 * WBPLANE + r1 * WBSTRIDE + c1) = *(const uint4*)(Wh + r1 * 256 + c1);
    *(uint4*)(wb + 1 * WBPLANE + r0 * WBSTRIDE + c0) = *(const uint4*)(Wl + r0 * 256 + c0);
    *(uint4*)(wb + 1 * WBPLANE + r1 * WBSTRIDE + c1) = *(const uint4*)(Wl + r1 * 256 + c1);
    __syncthreads();

    for (int t = 0; t < nt; t++) {
        uint4 v0, v1, v2, v3;
        const bool pf = (t + 1 < nt);
        if (pf) {
            const unsigned short* Wh1 = Wh + (size_t)(t + 1) * 16 * 256;
            const unsigned short* Wl1 = Wl + (size_t)(t + 1) * 16 * 256;
            v0 = *(const uint4*)(Wh1 + r0 * 256 + c0);
            v1 = *(const uint4*)(Wh1 + r1 * 256 + c1);
            v2 = *(const uint4*)(Wl1 + r0 * 256 + c0);
            v3 = *(const uint4*)(Wl1 + r1 * 256 + c1);
        }
        const int cur = t & 1;
        // build A fragments (fp32 -> bf16 hi/lo) for 2 m16 tiles
        u32 ah[2][4], al[2][4];
        const float* ab0 = src + (m0 + g) * sst + t * 16 + 2 * tt;
#pragma unroll
        for (int im = 0; im < 2; im++) {
            const float* ab = ab0 + im * 16 * sst;
            float2 p0 = *(const float2*)(ab);
            float2 p1 = *(const float2*)(ab + 8 * sst);
            float2 p2 = *(const float2*)(ab + 8);
            float2 p3 = *(const float2*)(ab + 8 * sst + 8);
            split2(p0.x, p0.y, ah[im][0], al[im][0]);
            split2(p1.x, p1.y, ah[im][1], al[im][1]);
            split2(p2.x, p2.y, ah[im][2], al[im][2]);
            split2(p3.x, p3.y, ah[im][3], al[im][3]);
        }
        const u32 hbase = wb_u32 + (u32)((cur * 2 + 0) * WBPLANE) * 2;
        const u32 lbase = wb_u32 + (u32)((cur * 2 + 1) * WBPLANE) * 2;
#pragma unroll
        for (int gg = 0; gg < 4; gg++) {
            u32 bh[4], bl[4];
            ldsm4t(bh, hbase + (u32)(b_off + gg * 16) * 2);
            ldsm4t(bl, lbase + (u32)(b_off + gg * 16) * 2);
#pragma unroll
            for (int im = 0; im < 2; im++) {
                mma_bf16(acc[im][2 * gg],     ah[im][0], ah[im][1], ah[im][2], ah[im][3], bh[0], bh[1]);
                mma_bf16(acc[im][2 * gg + 1], ah[im][0], ah[im][1], ah[im][2], ah[im][3], bh[2], bh[3]);
                mma_bf16(acc[im][2 * gg],     al[im][0], al[im][1], al[im][2], al[im][3], bh[0], bh[1]);
                mma_bf16(acc[im][2 * gg + 1], al[im][0], al[im][1], al[im][2], al[im][3], bh[2], bh[3]);
                mma_bf16(acc[im][2 * gg],     ah[im][0], ah[im][1], ah[im][2], ah[im][3], bl[0], bl[1]);
                mma_bf16(acc[im][2 * gg + 1], ah[im][0], ah[im][1], ah[im][2], ah[im][3], bl[2], bl[3]);
            }
        }
        if (pf) {
            const int nb = (t + 1) & 1;
            *(uint4*)(wb + (nb * 2 + 0) * WBPLANE + r0 * WBSTRIDE + c0) = v0;
            *(uint4*)(wb + (nb * 2 + 0) * WBPLANE + r1 * WBSTRIDE + c1) = v1;
            *(uint4*)(wb + (nb * 2 + 1) * WBPLANE + r0 * WBSTRIDE + c0) = v2;
            *(uint4*)(wb + (nb * 2 + 1) * WBPLANE + r1 * WBSTRIDE + c1) = v3;
        }
        __syncthreads();
    }
}

__device__ __forceinline__ void zero_acc_tc(float (&acc)[2][8][4]) {
#pragma unroll
    for (int im = 0; im < 2; im++)
#pragma unroll
        for (int j = 0; j < 8; j++)
#pragma unroll
            for (int q = 0; q < 4; q++) acc[im][j][q] = 0.f;
}

__device__ __forceinline__ void epi_relu(const float (&acc)[2][8][4],
                                         const float* __restrict__ bias,
                                         float* dst, int tid) {
    const int lane = tid & 31, wid = tid >> 5;
    const int m0 = (wid & 1) * 32, n_off = (wid >> 1) * 64;
    const int g = lane >> 2, tt = lane & 3;
#pragma unroll
    for (int im = 0; im < 2; im++)
#pragma unroll
        for (int j = 0; j < 8; j++) {
            int c = n_off + j * 8 + 2 * tt;
            float b0 = bias[c], b1 = bias[c + 1];
            float2 lo = make_float2(fmaxf(acc[im][j][0] + b0, 0.f),
                                    fmaxf(acc[im][j][1] + b1, 0.f));
            float2 hi = make_float2(fmaxf(acc[im][j][2] + b0, 0.f),
                                    fmaxf(acc[im][j][3] + b1, 0.f));
            *(float2*)(dst + (m0 + im * 16 + g) * 260 + c) = lo;
            *(float2*)(dst + (m0 + im * 16 + g + 8) * 260 + c) = hi;
        }
}

// ---------------- kernel 0: reset ---------------------------------------------
__global__ void reset_kernel() {
    if (threadIdx.x < NE) g_count[threadIdx.x] = 0;
}

// ---------------- kernel 0b: split weights to bf16 hi/lo ----------------------
__global__ void convert_weights(
    const float* __restrict__ ew0, const float* __restrict__ ew1,
    const float* __restrict__ ew2, const float* __restrict__ ew3,
    const float* __restrict__ ew4, const float* __restrict__ ew5,
    const float* __restrict__ ew6) {
    int idx = blockIdx.x * 256 + threadIdx.x;          // < NE*WROWS*256
    int e   = idx / (WROWS * 256);
    int rem = idx - e * (WROWS * 256);
    int r = rem >> 8, n = rem & 255;
    float w = 0.f;
    if (r < 96)        { int k = r;            if (k < 95) w = ew0[((size_t)e * 95 + k) * 256 + n]; }
    else if (r < 352)  { int k = r - 96;       w = ew1[((size_t)e * 256 + k) * 256 + n]; }
    else if (r < 608)  { int k = r - 352;      w = ew2[((size_t)e * 256 + k) * 256 + n]; }
    else if (r < 864)  { int k = r - 608;      w = ew3[((size_t)e * 256 + k) * 256 + n]; }
    else if (r < 1120) { int k = r - 864;      w = ew4[((size_t)e * 256 + k) * 256 + n]; }
    else if (r < 1376) { int k = r - 1120;     w = ew5[((size_t)e * 351 + k) * 256 + n]; }
    else if (r < 1472) { int k = 256 + (r - 1376); if (k < 351) w = ew5[((size_t)e * 351 + k) * 256 + n]; }
    else               { int k = r - 1472;     w = ew6[((size_t)e * 256 + k) * 256 + n]; }
    __nv_bfloat16 h = __float2bfloat16_rn(w);
    float hf = __bfloat162float(h);
    __nv_bfloat16 l = __float2bfloat16_rn(w - hf);
    g_wh[idx] = *(unsigned short*)&h;
    g_wl[idx] = *(unsigned short*)&l;
}

// ---------------- kernel 1: gate network + routing (fp32 scalar, exact) -------
typedef unsigned long long uu64;
__device__ __forceinline__ void ffma2(uu64& d, uu64 a, uu64 b) {
    asm("fma.rn.f32x2 %0, %1, %2, %0;" : "+l"(d) : "l"(a), "l"(b));
}
__device__ __forceinline__ uu64 dup2(float v) {
    uu64 r; asm("mov.b64 %0, {%1, %1};" : "=l"(r) : "r"(__float_as_uint(v))); return r;
}
__device__ __forceinline__ float2 unpk(uu64 v) {
    float2 f; asm("mov.b64 {%0, %1}, %2;" : "=f"(f.x), "=f"(f.y) : "l"(v)); return f;
}

__device__ __forceinline__ void load_wtile(const float* __restrict__ W, int t,
                                           int k_real, float* dst, int tid) {
#pragma unroll
    for (int p = 0; p < 4; p++) {
        int f4 = tid + p * 256;
        int row = f4 >> 6;
        int k = t * 16 + row;
        float4 v = make_float4(0.f, 0.f, 0.f, 0.f);
        if (k < k_real) v = *(const float4*)(W + (size_t)k * 256 + (f4 & 63) * 4);
        *(float4*)(dst + f4 * 4) = v;
    }
}

__device__ __forceinline__ void gemm_acc(const float* __restrict__ S, int ldS,
                                         const float* __restrict__ W,
                                         int k_pad, int k_real,
                                         float* w_s, uu64 acc[8][4], int tid) {
    const int tcol = tid & 31, trow = tid >> 5;
    const int ntiles = k_pad >> 4;
    load_wtile(W, 0, k_real, w_s, tid);
    __syncthreads();
    for (int t = 0; t < ntiles; t++) {
        const float* cur = w_s + (t & 1) * 4096;
        if (t + 1 < ntiles)
            load_wtile(W, t + 1, k_real, w_s + ((t + 1) & 1) * 4096, tid);
        const float* Sb = S + t * 16;
#pragma unroll
        for (int kk = 0; kk < 16; kk += 4) {
            float4 a4[8];
#pragma unroll
            for (int i = 0; i < 8; i++)
                a4[i] = *(const float4*)(Sb + (trow * 8 + i) * ldS + kk);
#pragma unroll
            for (int u = 0; u < 4; u++) {
                const uu64* bp = (const uu64*)(cur + (kk + u) * 256 + tcol * 8);
                uu64 b0 = bp[0], b1 = bp[1], b2 = bp[2], b3 = bp[3];
#pragma unroll
                for (int i = 0; i < 8; i++) {
                    float av = (u == 0) ? a4[i].x : (u == 1) ? a4[i].y
                             : (u == 2) ? a4[i].z : a4[i].w;
                    uu64 avv = dup2(av);
                    ffma2(acc[i][0], avv, b0);
                    ffma2(acc[i][1], avv, b1);
                    ffma2(acc[i][2], avv, b2);
                    ffma2(acc[i][3], avv, b3);
                }
            }
        }
        __syncthreads();
    }
}

__device__ __forceinline__ void zero_acc(uu64 acc[8][4]) {
#pragma unroll
    for (int i = 0; i < 8; i++)
#pragma unroll
        for (int j = 0; j < 4; j++) acc[i][j] = 0ull;
}

__device__ __forceinline__ void store_relu(const uu64 acc[8][4],
                                           const float* __restrict__ bias,
                                           float* dst, int tid) {
    const int tcol = tid & 31, trow = tid >> 5;
    float4 bb0 = *(const float4*)(bias + tcol * 8);
    float4 bb1 = *(const float4*)(bias + tcol * 8 + 4);
#pragma unroll
    for (int i = 0; i < 8; i++) {
        float2 p0 = unpk(acc[i][0]), p1 = unpk(acc[i][1]);
        float2 p2 = unpk(acc[i][2]), p3 = unpk(acc[i][3]);
        float4 v0, v1;
        v0.x = fmaxf(p0.x + bb0.x, 0.f); v0.y = fmaxf(p0.y + bb0.y, 0.f);
        v0.z = fmaxf(p1.x + bb0.z, 0.f); v0.w = fmaxf(p1.y + bb0.w, 0.f);
        v1.x = fmaxf(p2.x + bb1.x, 0.f); v1.y = fmaxf(p2.y + bb1.y, 0.f);
        v1.z = fmaxf(p3.x + bb1.z, 0.f); v1.w = fmaxf(p3.y + bb1.w, 0.f);
        *(float4*)(dst + (trow * 8 + i) * 256 + tcol * 8)     = v0;
        *(float4*)(dst + (trow * 8 + i) * 256 + tcol * 8 + 4) = v1;
    }
}

#define GATE_SMEM_F (20480 + 16384 + 8192)

__global__ __launch_bounds__(256, 1) void gate_kernel(
    const float* __restrict__ x,  const float* __restrict__ sl,
    const float* __restrict__ gw1, const float* __restrict__ gb1,
    const float* __restrict__ gw2, const float* __restrict__ gb2,
    const float* __restrict__ lng, const float* __restrict__ lnb,
    const float* __restrict__ gw3, const float* __restrict__ gb3) {
    extern __shared__ float sm[];
    float* gin  = sm;
    float* hbuf = sm + 20480;
    float* wsm  = sm + 20480 + 16384;
    const int tid = threadIdx.x;
    const int row0 = blockIdx.x * 64;
    const int tcol = tid & 31, trow = tid >> 5;

    for (int idx = tid; idx < 64 * 320; idx += 256) {
        int r = idx / 320, c = idx - r * 320;
        int gi = row0 + r;
        float v = 0.f;
        if (c < 63)       v = x[gi * 63 + c];
        else if (c < 319) v = sl[gi * 256 + (c - 63)];
        gin[idx] = v;
    }
    __syncthreads();

    uu64 acc[8][4];
    zero_acc(acc);
    gemm_acc(gin, 320, gw1, 320, 319, wsm, acc, tid);
    store_relu(acc, gb1, hbuf, tid);
    __syncthreads();

    zero_acc(acc);
    gemm_acc(hbuf, 256, gw2, 256, 256, wsm, acc, tid);
#pragma unroll
    for (int p = 0; p < 4; p++) {
#pragma unroll
        for (int i = 0; i < 8; i++) {
            float2 f = unpk(acc[i][p]);
            int c0 = tcol * 8 + p * 2;
            gin[(trow * 8 + i) * 257 + c0]     = f.x + gb2[c0];
            gin[(trow * 8 + i) * 257 + c0 + 1] = f.y + gb2[c0 + 1];
        }
    }
    __syncthreads();

    {
        int r = tid >> 2, sub = tid & 3;
        float* h2r = gin + r * 257;
        float s = 0.f;
#pragma unroll 8
        for (int k = 0; k < 64; k++) s += h2r[sub + 4 * k];
        s += __shfl_xor_sync(0xffffffffu, s, 1);
        s += __shfl_xor_sync(0xffffffffu, s, 2);
        float mu = s * (1.f / 256.f);
        float vv = 0.f;
#pragma unroll 8
        for (int k = 0; k < 64; k++) {
            float d = h2r[sub + 4 * k] - mu;
            vv += d * d;
        }
        vv += __shfl_xor_sync(0xffffffffu, vv, 1);
        vv += __shfl_xor_sync(0xffffffffu, vv, 2);
        float rstd = rsqrtf(vv * (1.f / 256.f) + 1e-5f);
#pragma unroll 8
        for (int k = 0; k < 64; k++) {
            int c = sub + 4 * k;
            float nv = (h2r[c] - mu) * rstd;
            h2r[c] = nv * lng[c] + lnb[c];
        }
    }
    __syncthreads();

    for (int task = tid; task < 512; task += 256) {
        int r = task >> 3, e = task & 7;
        float d = gb3[e];
        const float* h2r = gin + r * 257;
#pragma unroll 8
        for (int k = 0; k < 256; k++) d += h2r[k] * gw3[k * 8 + e];
        hbuf[r * 8 + e] = d;
    }
    __syncthreads();

    if (tid < 64) {
        int gi = row0 + tid;
        const float* lg = hbuf + tid * 8;
        float best = lg[0];
        int bi = 0;
#pragma unroll
        for (int e = 1; e < 8; e++) {
            float v = lg[e];
            if (v > best) { best = v; bi = e; }
        }
        float ssum = 0.f;
#pragma unroll
        for (int e = 0; e < 8; e++) ssum += expf(lg[e] - best);
        g_gv[gi] = 1.f / ssum;
        int pos = atomicAdd(&g_count[bi], 1);
        g_list[bi][pos] = gi;
    }
}

// ---------------- kernel 2: routed expert MLP (tensor-core split-bf16) --------
// smem: act fp32 [64][260] | h0 fp32 [64][100] | wstage bf16 2buf x 2split x 16 x 264
#define EXP_SMEM_F (16640 + 6400 + 8448)
#define EXP_TILES  (BPTS / 64 + NE)

__global__ __launch_bounds__(256, 1) void expert_kernel(
    const float* __restrict__ x,  const float* __restrict__ sl,
    const float* __restrict__ eb0, const float* __restrict__ eb1,
    const float* __restrict__ eb2, const float* __restrict__ eb3,
    const float* __restrict__ eb4, const float* __restrict__ eb5,
    const float* __restrict__ eb6,
    const float* __restrict__ ewo, const float* __restrict__ ebo,
    float* __restrict__ out) {
    int t = blockIdx.x;
    int e, base = 0, n = 0;
    for (e = 0; e < NE; e++) {
        n = g_count[e];
        int T = (n + 63) >> 6;
        if (t < base + T) break;
        base += T;
    }
    if (e == NE) return;
    const int start = (t - base) * 64;
    const int nrows = min(64, n - start);

    extern __shared__ float sm[];
    float* acts = sm;                      // 64*260
    float* h0s  = sm + 16640;              // 64*100
    unsigned short* wb = (unsigned short*)(sm + 16640 + 6400);
    const u32 wb_u32 = (u32)__cvta_generic_to_shared(wb);
    __shared__ int ridx[64];
    const int tid = threadIdx.x;

    if (tid < 64) ridx[tid] = (tid < nrows) ? g_list[e][start + tid] : -1;
    __syncthreads();

    // gather h0 = concat(x, latent chunk e) into [64][100], col95..99 zero
    for (int idx = tid; idx < 64 * 96; idx += 256) {
        int r = idx / 96, c = idx - r * 96;
        int gi = ridx[r];
        float v = 0.f;
        if (gi >= 0) {
            if (c < 63)      v = x[gi * 63 + c];
            else if (c < 95) v = sl[gi * 256 + e * CHUNKD + (c - 63)];
        }
        h0s[r * 100 + c] = v;
    }
    __syncthreads();

    const unsigned short* WH = g_wh + (size_t)e * WROWS * 256;
    const unsigned short* WL = g_wl + (size_t)e * WROWS * 256;
    float acc[2][8][4];

    // L0: h0 (Kpad=96) -> 256
    zero_acc_tc(acc);
    gemm_tc(acc, h0s, 100, 96, WH, WL, wb, wb_u32, tid);
    epi_relu(acc, eb0 + e * 256, acts, tid);
    __syncthreads();

    // L1..L4
    const float* bl4[4] = { eb1, eb2, eb3, eb4 };
#pragma unroll 1
    for (int l = 0; l < 4; l++) {
        zero_acc_tc(acc);
        gemm_tc(acc, acts, 260, 256, WH + (size_t)(96 + l * 256) * 256,
                WL + (size_t)(96 + l * 256) * 256, wb, wb_u32, tid);
        epi_relu(acc, bl4[l] + e * 256, acts, tid);
        __syncthreads();
    }

    // L5 (skip): act part + h0 part
    zero_acc_tc(acc);
    gemm_tc(acc, acts, 260, 256, WH + (size_t)1120 * 256, WL + (size_t)1120 * 256,
            wb, wb_u32, tid);
    gemm_tc(acc, h0s, 100, 96, WH + (size_t)1376 * 256, WL + (size_t)1376 * 256,
            wb, wb_u32, tid);
    epi_relu(acc, eb5 + e * 256, acts, tid);
    __syncthreads();

    // L6
    zero_acc_tc(acc);
    gemm_tc(acc, acts, 260, 256, WH + (size_t)1472 * 256, WL + (size_t)1472 * 256,
            wb, wb_u32, tid);
    epi_relu(acc, eb6 + e * 256, acts, tid);
    __syncthreads();

    // output head (fp32 scalar, tiny): y = act @ ewo[e] + ebo[e]
    {
        int r = tid >> 2, o = tid & 3;
        if (r < nrows) {
            float d = ebo[e * 4 + o];
            const float* ar = acts + r * 260;
            const float* wo = ewo + (size_t)e * 1024 + o;
#pragma unroll 8
            for (int k = 0; k < 256; k++) d += ar[k] * wo[k * 4];
            int gi = ridx[r];
            float comb = g_gv[gi] * expf(d);
            if (comb == 0.f) comb = EPSF;
            out[gi * 4 + o] = logf(comb);
        }
    }
}

// ---------------- launch -----------------------------------------------------
extern "C" void kernel_launch(void* const* d_in, const int* in_sizes, int n_in,
                              void* d_out, int out_size) {
    const float* x   = (const float*)d_in[0];
    const float* sl  = (const float*)d_in[1];
    const float* gw1 = (const float*)d_in[2];
    const float* gb1 = (const float*)d_in[3];
    const float* gw2 = (const float*)d_in[4];
    const float* gb2 = (const float*)d_in[5];
    const float* lng = (const float*)d_in[6];
    const float* lnb = (const float*)d_in[7];
    const float* gw3 = (const float*)d_in[8];
    const float* gb3 = (const float*)d_in[9];
    const float* ew0 = (const float*)d_in[10];
    const float* eb0 = (const float*)d_in[11];
    const float* ew1 = (const float*)d_in[12];
    const float* eb1 = (const float*)d_in[13];
    const float* ew2 = (const float*)d_in[14];
    const float* eb2 = (const float*)d_in[15];
    const float* ew3 = (const float*)d_in[16];
    const float* eb3 = (const float*)d_in[17];
    const float* ew4 = (const float*)d_in[18];
    const float* eb4 = (const float*)d_in[19];
    const float* ew5 = (const float*)d_in[20];
    const float* eb5 = (const float*)d_in[21];
    const float* ew6 = (const float*)d_in[22];
    const float* eb6 = (const float*)d_in[23];
    const float* ewo = (const float*)d_in[24];
    const float* ebo = (const float*)d_in[25];
    float* out = (float*)d_out;

    cudaFuncSetAttribute(gate_kernel, cudaFuncAttributeMaxDynamicSharedMemorySize,
                         GATE_SMEM_F * 4);
    cudaFuncSetAttribute(expert_kernel, cudaFuncAttributeMaxDynamicSharedMemorySize,
                         EXP_SMEM_F * 4);

    reset_kernel<<<1, 32>>>();
    convert_weights<<<NE * WROWS, 256>>>(ew0, ew1, ew2, ew3, ew4, ew5, ew6);
    gate_kernel<<<BPTS / 64, 256, GATE_SMEM_F * 4>>>(x, sl, gw1, gb1, gw2, gb2,
                                                     lng, lnb, gw3, gb3);
    expert_kernel<<<EXP_TILES, 256, EXP_SMEM_F * 4>>>(
        x, sl, eb0, eb1, eb2, eb3, eb4, eb5, eb6, ewo, ebo, out);
}